// round 3
// baseline (speedup 1.0000x reference)
#include <cuda_runtime.h>
#include <math.h>

// Problem geometry (fixed): B=8, C=3, H=W=512, TILE=128, STRIDE=64
// Cells: 8x8 of 64x64 per image; tile (ty,tx) covers cells {ty,ty+1}x{tx,tx+1}.
#define BSZ   8
#define NCH   3
#define HH    512
#define WW    512
#define PLANE (HH*WW)          // 262144
#define NCELL 8
#define NTILE 7
#define INV_TILE_ELEMS (1.0f/49152.0f)   // 1/(C*128*128)

__device__ float g_cellsum[BSZ * NCELL * NCELL];

__device__ __forceinline__ float tanh_approx(float x) {
    float y;
    asm("tanh.approx.f32 %0, %1;" : "=f"(y) : "f"(x));
    return y;
}

// ---------------------------------------------------------------------------
// Kernel 1: per-(b, cy, cx) 64x64 cell sum of (img_c0+img_c1+img_c2) * mask.
// 512 blocks x 256 threads, float4 loads. Measured at the L2 cap (~15TB/s).
// ---------------------------------------------------------------------------
__global__ void __launch_bounds__(256) cell_sum_kernel(
    const float* __restrict__ img, const float* __restrict__ mask)
{
    const int cx = blockIdx.x, cy = blockIdx.y, b = blockIdx.z;
    const int tid = threadIdx.x;

    const float* mb = mask + (b * HH + cy * 64) * WW + cx * 64;
    const float* ib = img + ((b * NCH) * HH + cy * 64) * WW + cx * 64;

    float acc = 0.0f;
    #pragma unroll
    for (int k = 0; k < 4; k++) {
        int f   = tid + k * 256;          // 0..1023 float4 slots
        int row = f >> 4;
        int col = (f & 15) << 2;
        int off = row * WW + col;
        float4 m  = *(const float4*)(mb + off);
        float4 i0 = *(const float4*)(ib + off);
        float4 i1 = *(const float4*)(ib + PLANE + off);
        float4 i2 = *(const float4*)(ib + 2 * PLANE + off);
        acc += (i0.x + i1.x + i2.x) * m.x
             + (i0.y + i1.y + i2.y) * m.y
             + (i0.z + i1.z + i2.z) * m.z
             + (i0.w + i1.w + i2.w) * m.w;
    }

    #pragma unroll
    for (int o = 16; o > 0; o >>= 1)
        acc += __shfl_xor_sync(0xffffffffu, acc, o);

    __shared__ float swarp[8];
    if ((tid & 31) == 0) swarp[tid >> 5] = acc;
    __syncthreads();
    if (tid == 0) {
        float v = swarp[0];
        #pragma unroll
        for (int w = 1; w < 8; w++) v += swarp[w];
        g_cellsum[(b * NCELL + cy) * NCELL + cx] = v;
    }
}

// ---------------------------------------------------------------------------
// Kernel 2: issue all main LDGs first; warp 0 alone builds per-cell averaged
// logits (cs -> lg -> lavg, __syncwarp-chained) while the loads fly; one
// __syncthreads; then 1 MUFU + ~4 FMA per pixel and a float4 store.
// IPT=2 float4/thread -> 2048 px/block -> 1024 blocks (7/SM).
// ---------------------------------------------------------------------------
#define FK_IPT 2
#define FK_TPB 256
#define FK_PX_PER_BLOCK (FK_TPB * FK_IPT * 4)   // 2048 pixels

__global__ void __launch_bounds__(FK_TPB) final_kernel(
    const float* __restrict__ mask, const float* __restrict__ gmap,
    float* __restrict__ out)
{
    __shared__ float cs[NCELL * NCELL];
    __shared__ float lg[NTILE * NTILE];
    __shared__ float lavg_cell[NCELL * NCELL];

    const int tid  = threadIdx.x;
    const int b    = blockIdx.y;
    const int base = blockIdx.x * FK_PX_PER_BLOCK;

    // ---- issue main loads FIRST (registers only; independent of shared) ----
    float4 m4[FK_IPT], g4[FK_IPT];
    int    idxv[FK_IPT];
    #pragma unroll
    for (int k = 0; k < FK_IPT; k++) {
        idxv[k] = base + (tid + k * FK_TPB) * 4;          // float4-aligned px
        m4[k] = *(const float4*)(mask + b * PLANE + idxv[k]);
        g4[k] = *(const float4*)(gmap + b * PLANE + idxv[k]);
    }

    // ---- warp 0: cellsum -> tile logits -> per-cell averaged logit ----
    if (tid < 32) {
        cs[tid]      = g_cellsum[b * NCELL * NCELL + tid];
        cs[tid + 32] = g_cellsum[b * NCELL * NCELL + tid + 32];
        __syncwarp();
        #pragma unroll
        for (int t = tid; t < NTILE * NTILE; t += 32) {
            int ty = t / NTILE, tx = t % NTILE;
            lg[t] = (cs[ty * NCELL + tx]       + cs[ty * NCELL + tx + 1] +
                     cs[(ty + 1) * NCELL + tx] + cs[(ty + 1) * NCELL + tx + 1])
                    * INV_TILE_ELEMS;
        }
        __syncwarp();
        #pragma unroll
        for (int c = tid; c < NCELL * NCELL; c += 32) {
            int cy = c >> 3, cx = c & 7;
            int ty0 = max(cy - 1, 0), ty1 = min(cy, NTILE - 1);
            int tx0 = max(cx - 1, 0), tx1 = min(cx, NTILE - 1);
            float s = 0.0f;
            for (int ty = ty0; ty <= ty1; ty++)
                for (int tx = tx0; tx <= tx1; tx++)
                    s += lg[ty * NTILE + tx];
            lavg_cell[c] = s * (1.0f / (float)((ty1 - ty0 + 1) * (tx1 - tx0 + 1)));
        }
    }
    __syncthreads();

    // ---- main math + store ----
    #pragma unroll
    for (int k = 0; k < FK_IPT; k++) {
        int cy = idxv[k] >> 15;                 // (idx/512)/64
        int cx = (idxv[k] & 511) >> 6;          // 4 px share one 64-cell
        float la = lavg_cell[cy * NCELL + cx];
        float4 o4;
        o4.x = m4[k].x * (0.5f * tanh_approx(0.25f * (g4[k].x + la * m4[k].x)) + 0.5f);
        o4.y = m4[k].y * (0.5f * tanh_approx(0.25f * (g4[k].y + la * m4[k].y)) + 0.5f);
        o4.z = m4[k].z * (0.5f * tanh_approx(0.25f * (g4[k].z + la * m4[k].z)) + 0.5f);
        o4.w = m4[k].w * (0.5f * tanh_approx(0.25f * (g4[k].w + la * m4[k].w)) + 0.5f);
        *(float4*)(out + b * PLANE + idxv[k]) = o4;
    }
}

// ---------------------------------------------------------------------------
// Inputs (metadata order):
//  0 image (8,3,512,512) f32 | 1 valid_mask (8,1,512,512) f32
//  2 global_heatmap (8,1,512,512) f32 | 3 tile_mask_bank (unused)
//  4 tile_mask_counts (unused) | 5 row_idx (unused) | 6 col_idx (unused)
// ---------------------------------------------------------------------------
extern "C" void kernel_launch(void* const* d_in, const int* in_sizes, int n_in,
                              void* d_out, int out_size)
{
    const float* image = (const float*)d_in[0];
    const float* mask  = (const float*)d_in[1];
    const float* gmap  = (const float*)d_in[2];
    float*       out   = (float*)d_out;

    cell_sum_kernel<<<dim3(NCELL, NCELL, BSZ), 256>>>(image, mask);
    final_kernel<<<dim3(PLANE / FK_PX_PER_BLOCK, BSZ), FK_TPB>>>(mask, gmap, out);
}